// round 15
// baseline (speedup 1.0000x reference)
#include <cuda_runtime.h>
#include <cuda_fp16.h>
#include <cstdint>

#define N_NODES 100000
#define PAD_NODES 100096
#define N_EDGES 1638400
#define IN_F    128
#define OUT_F   64
#define NUM_RELS 8
#define COLS    (NUM_RELS * OUT_F)   // 512
#define SCAN_BLOCKS ((N_NODES + 255) / 256)   // 391

// Scratch: xw[r][n][o] in fp16, layout ((r*N + n)*64 + o). 102.4 MB.
__device__ __half g_xw[(size_t)NUM_RELS * N_NODES * OUT_F];
// fp16 copies of inputs (feat padded; pad rows stay zero from .bss init)
__device__ __half g_featH[(size_t)PAD_NODES * IN_F];
__device__ __half g_wH[NUM_RELS * OUT_F * IN_F];

// CSR-by-destination scratch
__device__ int g_cnt[N_NODES];
__device__ int g_off[N_NODES + 1];
__device__ int g_cursor[N_NODES];
__device__ int g_bsum[512];
__device__ int g_perm[N_EDGES];     // packed rel*N_NODES + src, grouped by dst

__device__ __forceinline__ uint32_t smem_u32(const void* p) {
    uint32_t a;
    asm("{ .reg .u64 t; cvta.to.shared.u64 t, %1; cvt.u32.u64 %0, t; }" : "=r"(a) : "l"(p));
    return a;
}
#define CP_ASYNC16(dst, src) \
    asm volatile("cp.async.ca.shared.global [%0], [%1], 16;" :: "r"(dst), "l"(src))
#define CP_COMMIT() asm volatile("cp.async.commit_group;" ::: "memory")
#define CP_WAIT1()  asm volatile("cp.async.wait_group 1;" ::: "memory")
#define CP_WAIT0()  asm volatile("cp.async.wait_group 0;" ::: "memory")

// ---------------------------------------------------------------------------
// fp32 -> fp16 conversion of feat and W (8 elems per thread).
// ---------------------------------------------------------------------------
#define FEAT_CHUNKS (N_NODES * IN_F / 8)          // 1,600,000
#define W_CHUNKS    (NUM_RELS * OUT_F * IN_F / 8) // 8,192
__global__ void cvt_kernel(const float* __restrict__ feat, const float* __restrict__ W) {
    int i = blockIdx.x * blockDim.x + threadIdx.x;
    if (i < FEAT_CHUNKS) {
        float4 a = reinterpret_cast<const float4*>(feat)[i * 2];
        float4 b = reinterpret_cast<const float4*>(feat)[i * 2 + 1];
        __half2 h[4] = { __floats2half2_rn(a.x, a.y), __floats2half2_rn(a.z, a.w),
                         __floats2half2_rn(b.x, b.y), __floats2half2_rn(b.z, b.w) };
        reinterpret_cast<uint4*>(g_featH)[i] = *reinterpret_cast<uint4*>(h);
    } else if (i < FEAT_CHUNKS + W_CHUNKS) {
        int j = i - FEAT_CHUNKS;
        float4 a = reinterpret_cast<const float4*>(W)[j * 2];
        float4 b = reinterpret_cast<const float4*>(W)[j * 2 + 1];
        __half2 h[4] = { __floats2half2_rn(a.x, a.y), __floats2half2_rn(a.z, a.w),
                         __floats2half2_rn(b.x, b.y), __floats2half2_rn(b.z, b.w) };
        reinterpret_cast<uint4*>(g_wH)[j] = *reinterpret_cast<uint4*>(h);
    }
}

// ---------------------------------------------------------------------------
// CSR build: zero counters -> histogram -> 3-step scan -> fill
// ---------------------------------------------------------------------------
__global__ void init_cnt_kernel() {
    int i = blockIdx.x * blockDim.x + threadIdx.x;
    if (i < N_NODES) g_cnt[i] = 0;
}

__global__ void hist_kernel(const int* __restrict__ edst) {
    int e = blockIdx.x * blockDim.x + threadIdx.x;
    if (e < N_EDGES) atomicAdd(&g_cnt[edst[e]], 1);
}

__global__ void scan1_kernel() {
    __shared__ int s[256];
    int tid = threadIdx.x;
    int i = blockIdx.x * 256 + tid;
    int v = (i < N_NODES) ? g_cnt[i] : 0;
    s[tid] = v;
    __syncthreads();
#pragma unroll
    for (int d = 1; d < 256; d <<= 1) {
        int t = (tid >= d) ? s[tid - d] : 0;
        __syncthreads();
        s[tid] += t;
        __syncthreads();
    }
    if (i < N_NODES) g_off[i] = s[tid] - v;
    if (tid == 255) g_bsum[blockIdx.x] = s[255];
}

__global__ void scan2_kernel() {
    __shared__ int s[512];
    int tid = threadIdx.x;
    int v = (tid < SCAN_BLOCKS) ? g_bsum[tid] : 0;
    s[tid] = v;
    __syncthreads();
#pragma unroll
    for (int d = 1; d < 512; d <<= 1) {
        int t = (tid >= d) ? s[tid - d] : 0;
        __syncthreads();
        s[tid] += t;
        __syncthreads();
    }
    if (tid < SCAN_BLOCKS) g_bsum[tid] = s[tid] - v;
}

__global__ void scan3_kernel() {
    int i = blockIdx.x * 256 + threadIdx.x;
    if (i < N_NODES) {
        int o = g_off[i] + g_bsum[blockIdx.x];
        g_off[i] = o;
        g_cursor[i] = o;
    }
    if (i == 0) g_off[N_NODES] = N_EDGES;
}

__global__ void fill_kernel(const int* __restrict__ esrc,
                            const int* __restrict__ edst,
                            const int* __restrict__ etyp) {
    int e = blockIdx.x * blockDim.x + threadIdx.x;
    if (e < N_EDGES) {
        int d = edst[e];
        int pos = atomicAdd(&g_cursor[d], 1);
        g_perm[pos] = etyp[e] * N_NODES + esrc[e];
    }
}

// ---------------------------------------------------------------------------
// fp16 mma.sync GEMM, cp.async double-buffered.
// C[n][c] = sum_k featH[n][k] * wH[c][k], c = r*64+o.
// CTA tile 128x128 (grid: x=col tiles [fast], y=node tiles), BK=32,
// 256 threads = 8 warps, warp tile 64x32, m16n8k16 HMMA fp32 accum.
// SMEM stride 40 halves (80B): conflict-free fragment loads, 16B-aligned rows.
// ---------------------------------------------------------------------------
__global__ __launch_bounds__(256, 2)
void gemm_mma_kernel() {
    __shared__ __half As[2][128][40];
    __shared__ __half Bs[2][128][40];

    const int bc = blockIdx.x * 128;   // column tile (fast-varying -> A tile reuse)
    const int bm = blockIdx.y * 128;   // node tile
    const int tid = threadIdx.x;
    const int wid = tid >> 5;
    const int lane = tid & 31;
    const int g = lane >> 2;
    const int t = lane & 3;
    const int warp_m = (wid & 1) * 64;
    const int warp_n = (wid >> 1) * 32;

    // cp.async chunk coords: 512 16B-chunks per tile, 2 per thread.
    const int j0 = tid * 2;
    const int rowA0 = j0 >> 2, kqA0 = j0 & 3;
    const int rowA1 = (j0 + 1) >> 2, kqA1 = (j0 + 1) & 3;

    float acc[4][4][4];
#pragma unroll
    for (int i = 0; i < 4; i++)
#pragma unroll
        for (int j = 0; j < 4; j++)
#pragma unroll
            for (int c = 0; c < 4; c++) acc[i][j][c] = 0.f;

    auto issue = [&](int k0, int buf) {
        // A: featH[bm+row][k0 + kq*8], 16B each
        CP_ASYNC16(smem_u32(&As[buf][rowA0][kqA0 * 8]),
                   g_featH + (size_t)(bm + rowA0) * IN_F + k0 + kqA0 * 8);
        CP_ASYNC16(smem_u32(&As[buf][rowA1][kqA1 * 8]),
                   g_featH + (size_t)(bm + rowA1) * IN_F + k0 + kqA1 * 8);
        // B: wH[bc+col][k0 + kq*8]
        CP_ASYNC16(smem_u32(&Bs[buf][rowA0][kqA0 * 8]),
                   g_wH + (size_t)(bc + rowA0) * IN_F + k0 + kqA0 * 8);
        CP_ASYNC16(smem_u32(&Bs[buf][rowA1][kqA1 * 8]),
                   g_wH + (size_t)(bc + rowA1) * IN_F + k0 + kqA1 * 8);
    };

    issue(0, 0);
    CP_COMMIT();

    for (int kt = 0; kt < 4; kt++) {
        const int buf = kt & 1;
        if (kt < 3) {
            issue((kt + 1) * 32, buf ^ 1);
            CP_COMMIT();
            CP_WAIT1();
        } else {
            CP_WAIT0();
        }
        __syncthreads();

#pragma unroll
        for (int ks = 0; ks < 2; ks++) {
            const int kb = ks * 16;
            uint32_t af[4][4];
#pragma unroll
            for (int mt = 0; mt < 4; mt++) {
                int row = warp_m + mt * 16 + g;
                af[mt][0] = *reinterpret_cast<const uint32_t*>(&As[buf][row][kb + 2 * t]);
                af[mt][1] = *reinterpret_cast<const uint32_t*>(&As[buf][row + 8][kb + 2 * t]);
                af[mt][2] = *reinterpret_cast<const uint32_t*>(&As[buf][row][kb + 2 * t + 8]);
                af[mt][3] = *reinterpret_cast<const uint32_t*>(&As[buf][row + 8][kb + 2 * t + 8]);
            }
            uint32_t bf[4][2];
#pragma unroll
            for (int nt = 0; nt < 4; nt++) {
                int col = warp_n + nt * 8 + g;
                bf[nt][0] = *reinterpret_cast<const uint32_t*>(&Bs[buf][col][kb + 2 * t]);
                bf[nt][1] = *reinterpret_cast<const uint32_t*>(&Bs[buf][col][kb + 2 * t + 8]);
            }
#pragma unroll
            for (int mt = 0; mt < 4; mt++)
#pragma unroll
                for (int nt = 0; nt < 4; nt++) {
                    asm volatile(
                        "mma.sync.aligned.m16n8k16.row.col.f32.f16.f16.f32 "
                        "{%0,%1,%2,%3}, {%4,%5,%6,%7}, {%8,%9}, {%0,%1,%2,%3};"
                        : "+f"(acc[mt][nt][0]), "+f"(acc[mt][nt][1]),
                          "+f"(acc[mt][nt][2]), "+f"(acc[mt][nt][3])
                        : "r"(af[mt][0]), "r"(af[mt][1]), "r"(af[mt][2]), "r"(af[mt][3]),
                          "r"(bf[nt][0]), "r"(bf[nt][1]));
                }
        }
        __syncthreads();
    }

    // Store fp16: c0=C[g][2t] c1=C[g][2t+1] (one half2 = 4B), rows g and g+8.
#pragma unroll
    for (int mt = 0; mt < 4; mt++) {
#pragma unroll
        for (int nt = 0; nt < 4; nt++) {
            int col = bc + warp_n + nt * 8 + t * 2;
            int rel = col >> 6;
            int o   = col & 63;
            int row0 = bm + warp_m + mt * 16 + g;
            if (row0 < N_NODES) {
                __half2* p = reinterpret_cast<__half2*>(
                    g_xw + ((size_t)rel * N_NODES + row0) * OUT_F + o);
                *p = __floats2half2_rn(acc[mt][nt][0], acc[mt][nt][1]);
            }
            int row1 = row0 + 8;
            if (row1 < N_NODES) {
                __half2* p = reinterpret_cast<__half2*>(
                    g_xw + ((size_t)rel * N_NODES + row1) * OUT_F + o);
                *p = __floats2half2_rn(acc[mt][nt][2], acc[mt][nt][3]);
            }
        }
    }
}

// ---------------------------------------------------------------------------
// Reduce: one warp per destination node. Lane l owns output cols 2l, 2l+1.
// Unroll 16 with perm prefetch for deep MLP. fp32 accumulate.
// ---------------------------------------------------------------------------
__global__ __launch_bounds__(256)
void reduce_kernel(float* __restrict__ out) {
    int warp = (blockIdx.x * 256 + threadIdx.x) >> 5;   // node id, exact cover
    int lane = threadIdx.x & 31;
    int beg = g_off[warp];
    int end = g_off[warp + 1];

    const __half2* xw2 = reinterpret_cast<const __half2*>(g_xw);
    float2 acc = make_float2(0.f, 0.f);
    int j = beg;
    for (; j + 16 <= end; j += 16) {
        int p[16];
#pragma unroll
        for (int u = 0; u < 16; u++) p[u] = g_perm[j + u];
        float2 v[16];
#pragma unroll
        for (int u = 0; u < 16; u++)
            v[u] = __half22float2(xw2[(size_t)p[u] * (OUT_F / 2) + lane]);
#pragma unroll
        for (int u = 0; u < 16; u++) { acc.x += v[u].x; acc.y += v[u].y; }
    }
    for (; j + 4 <= end; j += 4) {
        int p[4];
#pragma unroll
        for (int u = 0; u < 4; u++) p[u] = g_perm[j + u];
        float2 v[4];
#pragma unroll
        for (int u = 0; u < 4; u++)
            v[u] = __half22float2(xw2[(size_t)p[u] * (OUT_F / 2) + lane]);
#pragma unroll
        for (int u = 0; u < 4; u++) { acc.x += v[u].x; acc.y += v[u].y; }
    }
    for (; j < end; j++) {
        float2 v = __half22float2(xw2[(size_t)g_perm[j] * (OUT_F / 2) + lane]);
        acc.x += v.x; acc.y += v.y;
    }
    *reinterpret_cast<float2*>(out + (size_t)warp * OUT_F + lane * 2) = acc;
}

extern "C" void kernel_launch(void* const* d_in, const int* in_sizes, int n_in,
                              void* d_out, int out_size) {
    const float* feat = (const float*)d_in[0];
    const float* W    = (const float*)d_in[1];
    const int* esrc   = (const int*)d_in[2];
    const int* edst   = (const int*)d_in[3];
    const int* etyp   = (const int*)d_in[4];
    float* out        = (float*)d_out;

    const int nb_node = (N_NODES + 255) / 256;   // 391
    const int nb_edge = (N_EDGES + 255) / 256;   // 6400
    const int nb_cvt  = (FEAT_CHUNKS + W_CHUNKS + 255) / 256;

    // fp16 copies of feat / W
    cvt_kernel<<<nb_cvt, 256>>>(feat, W);

    // CSR build by destination
    init_cnt_kernel<<<nb_node, 256>>>();
    hist_kernel<<<nb_edge, 256>>>(edst);
    scan1_kernel<<<SCAN_BLOCKS, 256>>>();
    scan2_kernel<<<1, 512>>>();
    scan3_kernel<<<SCAN_BLOCKS, 256>>>();
    fill_kernel<<<nb_edge, 256>>>(esrc, edst, etyp);

    // xw[r][n][o] = featH @ wH[r]^T via fp16 mma.sync + cp.async pipeline
    dim3 ggrid(COLS / 128, (N_NODES + 127) / 128);   // (4, 782), col tiles fast
    gemm_mma_kernel<<<ggrid, 256>>>();

    // Gather + register reduce per destination node (writes every output elem)
    reduce_kernel<<<(N_NODES * 32) / 256, 256>>>(out);
}

// round 16
// speedup vs baseline: 1.0904x; 1.0904x over previous
#include <cuda_runtime.h>
#include <cuda_fp16.h>
#include <cstdint>

#define N_NODES 100000
#define PAD_NODES 100096
#define N_EDGES 1638400
#define IN_F    128
#define OUT_F   64
#define NUM_RELS 8
#define COLS    (NUM_RELS * OUT_F)   // 512
#define SCAN_BLOCKS ((N_NODES + 255) / 256)   // 391

// Scratch: xw[r][n][o] in fp16, layout ((r*N + n)*64 + o). 102.4 MB.
__device__ __half g_xw[(size_t)NUM_RELS * N_NODES * OUT_F];
// fp16 copies of inputs (feat padded; pad rows stay zero from .bss init)
__device__ __half g_featH[(size_t)PAD_NODES * IN_F];
__device__ __half g_wH[NUM_RELS * OUT_F * IN_F];

// CSR-by-destination scratch. g_cnt starts zero (.bss) and is re-zeroed by
// scan1 on every call, so the zero-before-hist invariant holds deterministically.
__device__ int g_cnt[N_NODES];
__device__ int g_off[N_NODES + 1];
__device__ int g_cursor[N_NODES];
__device__ int g_bsum[512];
__device__ int g_perm[N_EDGES];     // packed rel*N_NODES + src, grouped by dst

__device__ __forceinline__ uint32_t smem_u32(const void* p) {
    uint32_t a;
    asm("{ .reg .u64 t; cvta.to.shared.u64 t, %1; cvt.u32.u64 %0, t; }" : "=r"(a) : "l"(p));
    return a;
}
#define CP_ASYNC16(dst, src) \
    asm volatile("cp.async.ca.shared.global [%0], [%1], 16;" :: "r"(dst), "l"(src))
#define CP_COMMIT() asm volatile("cp.async.commit_group;" ::: "memory")
#define CP_WAIT1()  asm volatile("cp.async.wait_group 1;" ::: "memory")
#define CP_WAIT0()  asm volatile("cp.async.wait_group 0;" ::: "memory")

// ---------------------------------------------------------------------------
// fp32 -> fp16 conversion of feat and W (8 elems per thread).
// ---------------------------------------------------------------------------
#define FEAT_CHUNKS (N_NODES * IN_F / 8)          // 1,600,000
#define W_CHUNKS    (NUM_RELS * OUT_F * IN_F / 8) // 8,192
__global__ void cvt_kernel(const float* __restrict__ feat, const float* __restrict__ W) {
    int i = blockIdx.x * blockDim.x + threadIdx.x;
    if (i < FEAT_CHUNKS) {
        float4 a = reinterpret_cast<const float4*>(feat)[i * 2];
        float4 b = reinterpret_cast<const float4*>(feat)[i * 2 + 1];
        __half2 h[4] = { __floats2half2_rn(a.x, a.y), __floats2half2_rn(a.z, a.w),
                         __floats2half2_rn(b.x, b.y), __floats2half2_rn(b.z, b.w) };
        reinterpret_cast<uint4*>(g_featH)[i] = *reinterpret_cast<uint4*>(h);
    } else if (i < FEAT_CHUNKS + W_CHUNKS) {
        int j = i - FEAT_CHUNKS;
        float4 a = reinterpret_cast<const float4*>(W)[j * 2];
        float4 b = reinterpret_cast<const float4*>(W)[j * 2 + 1];
        __half2 h[4] = { __floats2half2_rn(a.x, a.y), __floats2half2_rn(a.z, a.w),
                         __floats2half2_rn(b.x, b.y), __floats2half2_rn(b.z, b.w) };
        reinterpret_cast<uint4*>(g_wH)[j] = *reinterpret_cast<uint4*>(h);
    }
}

// ---------------------------------------------------------------------------
// CSR build: histogram -> 3-step scan (scan1 re-zeros cnt) -> fill
// ---------------------------------------------------------------------------
__global__ void hist_kernel(const int* __restrict__ edst) {
    int e = blockIdx.x * blockDim.x + threadIdx.x;
    if (e < N_EDGES) atomicAdd(&g_cnt[edst[e]], 1);
}

__global__ void scan1_kernel() {
    __shared__ int s[256];
    int tid = threadIdx.x;
    int i = blockIdx.x * 256 + tid;
    int v = 0;
    if (i < N_NODES) { v = g_cnt[i]; g_cnt[i] = 0; }   // read + restore invariant
    s[tid] = v;
    __syncthreads();
#pragma unroll
    for (int d = 1; d < 256; d <<= 1) {
        int t = (tid >= d) ? s[tid - d] : 0;
        __syncthreads();
        s[tid] += t;
        __syncthreads();
    }
    if (i < N_NODES) g_off[i] = s[tid] - v;
    if (tid == 255) g_bsum[blockIdx.x] = s[255];
}

__global__ void scan2_kernel() {
    __shared__ int s[512];
    int tid = threadIdx.x;
    int v = (tid < SCAN_BLOCKS) ? g_bsum[tid] : 0;
    s[tid] = v;
    __syncthreads();
#pragma unroll
    for (int d = 1; d < 512; d <<= 1) {
        int t = (tid >= d) ? s[tid - d] : 0;
        __syncthreads();
        s[tid] += t;
        __syncthreads();
    }
    if (tid < SCAN_BLOCKS) g_bsum[tid] = s[tid] - v;
}

__global__ void scan3_kernel() {
    int i = blockIdx.x * 256 + threadIdx.x;
    if (i < N_NODES) {
        int o = g_off[i] + g_bsum[blockIdx.x];
        g_off[i] = o;
        g_cursor[i] = o;
    }
    if (i == 0) g_off[N_NODES] = N_EDGES;
}

__global__ void fill_kernel(const int* __restrict__ esrc,
                            const int* __restrict__ edst,
                            const int* __restrict__ etyp) {
    int e = blockIdx.x * blockDim.x + threadIdx.x;
    if (e < N_EDGES) {
        int d = edst[e];
        int pos = atomicAdd(&g_cursor[d], 1);
        g_perm[pos] = etyp[e] * N_NODES + esrc[e];
    }
}

// ---------------------------------------------------------------------------
// fp16 mma.sync GEMM, cp.async double-buffered (unchanged from R15).
// ---------------------------------------------------------------------------
__global__ __launch_bounds__(256, 2)
void gemm_mma_kernel() {
    __shared__ __half As[2][128][40];
    __shared__ __half Bs[2][128][40];

    const int bc = blockIdx.x * 128;
    const int bm = blockIdx.y * 128;
    const int tid = threadIdx.x;
    const int wid = tid >> 5;
    const int lane = tid & 31;
    const int g = lane >> 2;
    const int t = lane & 3;
    const int warp_m = (wid & 1) * 64;
    const int warp_n = (wid >> 1) * 32;

    const int j0 = tid * 2;
    const int rowA0 = j0 >> 2, kqA0 = j0 & 3;
    const int rowA1 = (j0 + 1) >> 2, kqA1 = (j0 + 1) & 3;

    float acc[4][4][4];
#pragma unroll
    for (int i = 0; i < 4; i++)
#pragma unroll
        for (int j = 0; j < 4; j++)
#pragma unroll
            for (int c = 0; c < 4; c++) acc[i][j][c] = 0.f;

    auto issue = [&](int k0, int buf) {
        CP_ASYNC16(smem_u32(&As[buf][rowA0][kqA0 * 8]),
                   g_featH + (size_t)(bm + rowA0) * IN_F + k0 + kqA0 * 8);
        CP_ASYNC16(smem_u32(&As[buf][rowA1][kqA1 * 8]),
                   g_featH + (size_t)(bm + rowA1) * IN_F + k0 + kqA1 * 8);
        CP_ASYNC16(smem_u32(&Bs[buf][rowA0][kqA0 * 8]),
                   g_wH + (size_t)(bc + rowA0) * IN_F + k0 + kqA0 * 8);
        CP_ASYNC16(smem_u32(&Bs[buf][rowA1][kqA1 * 8]),
                   g_wH + (size_t)(bc + rowA1) * IN_F + k0 + kqA1 * 8);
    };

    issue(0, 0);
    CP_COMMIT();

    for (int kt = 0; kt < 4; kt++) {
        const int buf = kt & 1;
        if (kt < 3) {
            issue((kt + 1) * 32, buf ^ 1);
            CP_COMMIT();
            CP_WAIT1();
        } else {
            CP_WAIT0();
        }
        __syncthreads();

#pragma unroll
        for (int ks = 0; ks < 2; ks++) {
            const int kb = ks * 16;
            uint32_t af[4][4];
#pragma unroll
            for (int mt = 0; mt < 4; mt++) {
                int row = warp_m + mt * 16 + g;
                af[mt][0] = *reinterpret_cast<const uint32_t*>(&As[buf][row][kb + 2 * t]);
                af[mt][1] = *reinterpret_cast<const uint32_t*>(&As[buf][row + 8][kb + 2 * t]);
                af[mt][2] = *reinterpret_cast<const uint32_t*>(&As[buf][row][kb + 2 * t + 8]);
                af[mt][3] = *reinterpret_cast<const uint32_t*>(&As[buf][row + 8][kb + 2 * t + 8]);
            }
            uint32_t bf[4][2];
#pragma unroll
            for (int nt = 0; nt < 4; nt++) {
                int col = warp_n + nt * 8 + g;
                bf[nt][0] = *reinterpret_cast<const uint32_t*>(&Bs[buf][col][kb + 2 * t]);
                bf[nt][1] = *reinterpret_cast<const uint32_t*>(&Bs[buf][col][kb + 2 * t + 8]);
            }
#pragma unroll
            for (int mt = 0; mt < 4; mt++)
#pragma unroll
                for (int nt = 0; nt < 4; nt++) {
                    asm volatile(
                        "mma.sync.aligned.m16n8k16.row.col.f32.f16.f16.f32 "
                        "{%0,%1,%2,%3}, {%4,%5,%6,%7}, {%8,%9}, {%0,%1,%2,%3};"
                        : "+f"(acc[mt][nt][0]), "+f"(acc[mt][nt][1]),
                          "+f"(acc[mt][nt][2]), "+f"(acc[mt][nt][3])
                        : "r"(af[mt][0]), "r"(af[mt][1]), "r"(af[mt][2]), "r"(af[mt][3]),
                          "r"(bf[nt][0]), "r"(bf[nt][1]));
                }
        }
        __syncthreads();
    }

#pragma unroll
    for (int mt = 0; mt < 4; mt++) {
#pragma unroll
        for (int nt = 0; nt < 4; nt++) {
            int col = bc + warp_n + nt * 8 + t * 2;
            int rel = col >> 6;
            int o   = col & 63;
            int row0 = bm + warp_m + mt * 16 + g;
            if (row0 < N_NODES) {
                __half2* p = reinterpret_cast<__half2*>(
                    g_xw + ((size_t)rel * N_NODES + row0) * OUT_F + o);
                *p = __floats2half2_rn(acc[mt][nt][0], acc[mt][nt][1]);
            }
            int row1 = row0 + 8;
            if (row1 < N_NODES) {
                __half2* p = reinterpret_cast<__half2*>(
                    g_xw + ((size_t)rel * N_NODES + row1) * OUT_F + o);
                *p = __floats2half2_rn(acc[mt][nt][2], acc[mt][nt][3]);
            }
        }
    }
}

// ---------------------------------------------------------------------------
// Reduce: one warp per node, 2 edges per iteration (half-warps), 8B per lane.
// Lane = 16*half + c; lane covers output cols 4c..4c+3 of its half's edge.
// shfl_xor(16) combines halves; lanes 0-15 store coalesced float4.
// ---------------------------------------------------------------------------
__global__ __launch_bounds__(256)
void reduce_kernel(float* __restrict__ out) {
    int warp = (blockIdx.x * 256 + threadIdx.x) >> 5;   // node id, exact cover
    int lane = threadIdx.x & 31;
    int half = lane >> 4;
    int c = lane & 15;
    int beg = g_off[warp];
    int end = g_off[warp + 1];

    const uint2* xw4 = reinterpret_cast<const uint2*>(g_xw);   // 8B units, row=16
    float4 acc = make_float4(0.f, 0.f, 0.f, 0.f);

#define LOADV(e, q) { int _p = g_perm[e]; (q) = xw4[(size_t)_p * 16 + c]; }
#define ADDV(q) { \
    __half2 _h0 = *reinterpret_cast<const __half2*>(&(q).x); \
    __half2 _h1 = *reinterpret_cast<const __half2*>(&(q).y); \
    float2 _f0 = __half22float2(_h0), _f1 = __half22float2(_h1); \
    acc.x += _f0.x; acc.y += _f0.y; acc.z += _f1.x; acc.w += _f1.y; }

    int j = beg;
    for (; j + 16 <= end; j += 16) {
        uint2 q[8];
#pragma unroll
        for (int u = 0; u < 8; u++) LOADV(j + 2 * u + half, q[u]);
#pragma unroll
        for (int u = 0; u < 8; u++) ADDV(q[u]);
    }
    for (; j + 2 <= end; j += 2) {
        uint2 q;
        LOADV(j + half, q);
        ADDV(q);
    }
    if (j < end && half == 0) {
        uint2 q;
        LOADV(j, q);
        ADDV(q);
    }
#undef LOADV
#undef ADDV

    acc.x += __shfl_xor_sync(0xFFFFFFFFu, acc.x, 16);
    acc.y += __shfl_xor_sync(0xFFFFFFFFu, acc.y, 16);
    acc.z += __shfl_xor_sync(0xFFFFFFFFu, acc.z, 16);
    acc.w += __shfl_xor_sync(0xFFFFFFFFu, acc.w, 16);

    if (half == 0)
        reinterpret_cast<float4*>(out)[(size_t)warp * (OUT_F / 4) + c] = acc;
}

extern "C" void kernel_launch(void* const* d_in, const int* in_sizes, int n_in,
                              void* d_out, int out_size) {
    const float* feat = (const float*)d_in[0];
    const float* W    = (const float*)d_in[1];
    const int* esrc   = (const int*)d_in[2];
    const int* edst   = (const int*)d_in[3];
    const int* etyp   = (const int*)d_in[4];
    float* out        = (float*)d_out;

    const int nb_edge = (N_EDGES + 255) / 256;   // 6400
    const int nb_cvt  = (FEAT_CHUNKS + W_CHUNKS + 255) / 256;

    // Fork a side stream for the CSR build so it overlaps cvt+GEMM.
    // (Host-side stream/event objects only; no device allocation.)
    cudaStream_t s1;
    cudaEvent_t evFork, evJoin;
    cudaStreamCreateWithFlags(&s1, cudaStreamNonBlocking);
    cudaEventCreateWithFlags(&evFork, cudaEventDisableTiming);
    cudaEventCreateWithFlags(&evJoin, cudaEventDisableTiming);

    cudaEventRecord(evFork, 0);
    cudaStreamWaitEvent(s1, evFork, 0);

    // side stream: CSR build by destination
    hist_kernel<<<nb_edge, 256, 0, s1>>>(edst);
    scan1_kernel<<<SCAN_BLOCKS, 256, 0, s1>>>();
    scan2_kernel<<<1, 512, 0, s1>>>();
    scan3_kernel<<<SCAN_BLOCKS, 256, 0, s1>>>();
    fill_kernel<<<nb_edge, 256, 0, s1>>>(esrc, edst, etyp);
    cudaEventRecord(evJoin, s1);

    // main stream: fp16 convert + GEMM
    cvt_kernel<<<nb_cvt, 256>>>(feat, W);
    dim3 ggrid(COLS / 128, (N_NODES + 127) / 128);   // (4, 782)
    gemm_mma_kernel<<<ggrid, 256>>>();

    // join, then gather + register reduce per destination node
    cudaStreamWaitEvent(0, evJoin, 0);
    reduce_kernel<<<(N_NODES * 32) / 256, 256>>>(out);
}

// round 17
// speedup vs baseline: 1.0929x; 1.0022x over previous
#include <cuda_runtime.h>
#include <cuda_fp16.h>
#include <cstdint>

#define N_NODES 100000
#define N_EDGES 1638400
#define IN_F    128
#define OUT_F   64
#define NUM_RELS 8
#define COLS    (NUM_RELS * OUT_F)   // 512
#define SCAN_BLOCKS ((N_NODES + 255) / 256)   // 391

// Scratch: xw[r][n][o] in fp16, layout ((r*N + n)*64 + o). 102.4 MB.
__device__ __half g_xw[(size_t)NUM_RELS * N_NODES * OUT_F];

// CSR-by-destination scratch. g_cnt starts zero (.bss) and is re-zeroed by
// scan1 on every call, so the zero-before-hist invariant holds deterministically.
__device__ int g_cnt[N_NODES];
__device__ int g_off[N_NODES + 1];
__device__ int g_cursor[N_NODES];
__device__ int g_bsum[512];
__device__ int g_perm[N_EDGES];     // packed rel*N_NODES + src, grouped by dst

// ---------------------------------------------------------------------------
// CSR build: histogram -> 3-step scan (scan1 re-zeros cnt) -> fill
// ---------------------------------------------------------------------------
__global__ void hist_kernel(const int* __restrict__ edst) {
    int e = blockIdx.x * blockDim.x + threadIdx.x;
    if (e < N_EDGES) atomicAdd(&g_cnt[edst[e]], 1);
}

__global__ void scan1_kernel() {
    __shared__ int s[256];
    int tid = threadIdx.x;
    int i = blockIdx.x * 256 + tid;
    int v = 0;
    if (i < N_NODES) { v = g_cnt[i]; g_cnt[i] = 0; }   // read + restore invariant
    s[tid] = v;
    __syncthreads();
#pragma unroll
    for (int d = 1; d < 256; d <<= 1) {
        int t = (tid >= d) ? s[tid - d] : 0;
        __syncthreads();
        s[tid] += t;
        __syncthreads();
    }
    if (i < N_NODES) g_off[i] = s[tid] - v;
    if (tid == 255) g_bsum[blockIdx.x] = s[255];
}

__global__ void scan2_kernel() {
    __shared__ int s[512];
    int tid = threadIdx.x;
    int v = (tid < SCAN_BLOCKS) ? g_bsum[tid] : 0;
    s[tid] = v;
    __syncthreads();
#pragma unroll
    for (int d = 1; d < 512; d <<= 1) {
        int t = (tid >= d) ? s[tid - d] : 0;
        __syncthreads();
        s[tid] += t;
        __syncthreads();
    }
    if (tid < SCAN_BLOCKS) g_bsum[tid] = s[tid] - v;
}

__global__ void scan3_kernel() {
    int i = blockIdx.x * 256 + threadIdx.x;
    if (i < N_NODES) {
        int o = g_off[i] + g_bsum[blockIdx.x];
        g_off[i] = o;
        g_cursor[i] = o;
    }
    if (i == 0) g_off[N_NODES] = N_EDGES;
}

__global__ void fill_kernel(const int* __restrict__ esrc,
                            const int* __restrict__ edst,
                            const int* __restrict__ etyp) {
    int e = blockIdx.x * blockDim.x + threadIdx.x;
    if (e < N_EDGES) {
        int d = edst[e];
        int pos = atomicAdd(&g_cursor[d], 1);
        g_perm[pos] = etyp[e] * N_NODES + esrc[e];
    }
}

// ---------------------------------------------------------------------------
// fp16 mma.sync GEMM with fused fp32->fp16 convert (R10 body, swapped grid).
// C[n][c] = sum_k feat[n][k] * W[r][o][k], c = r*64+o.
// CTA tile 128x128, BK=32, 256 threads = 8 warps, warp tile 64x32.
// ---------------------------------------------------------------------------
__global__ __launch_bounds__(256, 2)
void gemm_mma_kernel(const float* __restrict__ feat, const float* __restrict__ W) {
    __shared__ __half As[128][40];   // [row][k], stride 40 -> conflict-free frags
    __shared__ __half Bs[128][40];   // [col][k]

    const int bc = blockIdx.x * 128;   // col tile fast-varying -> A tile L2 reuse
    const int bm = blockIdx.y * 128;
    const int tid = threadIdx.x;
    const int wid = tid >> 5;
    const int lane = tid & 31;
    const int g = lane >> 2;
    const int t = lane & 3;
    const int warp_m = (wid & 1) * 64;
    const int warp_n = (wid >> 1) * 32;

    float acc[4][4][4];
#pragma unroll
    for (int i = 0; i < 4; i++)
#pragma unroll
        for (int j = 0; j < 4; j++)
#pragma unroll
            for (int c = 0; c < 4; c++) acc[i][j][c] = 0.f;

    for (int k0 = 0; k0 < IN_F; k0 += 32) {
#pragma unroll
        for (int j = tid; j < 1024; j += 256) {
            int row = j >> 3;
            int kq  = j & 7;
            int n   = bm + row;
            float4 v = make_float4(0.f, 0.f, 0.f, 0.f);
            if (n < N_NODES)
                v = *reinterpret_cast<const float4*>(feat + (size_t)n * IN_F + k0 + kq * 4);
            __half2* p = reinterpret_cast<__half2*>(&As[row][kq * 4]);
            p[0] = __floats2half2_rn(v.x, v.y);
            p[1] = __floats2half2_rn(v.z, v.w);
        }
#pragma unroll
        for (int j = tid; j < 1024; j += 256) {
            int col = j >> 3;
            int kq  = j & 7;
            int c   = bc + col;
            int r   = c >> 6;
            int o   = c & 63;
            float4 v = *reinterpret_cast<const float4*>(
                W + ((size_t)r * OUT_F + o) * IN_F + k0 + kq * 4);
            __half2* p = reinterpret_cast<__half2*>(&Bs[col][kq * 4]);
            p[0] = __floats2half2_rn(v.x, v.y);
            p[1] = __floats2half2_rn(v.z, v.w);
        }
        __syncthreads();

#pragma unroll
        for (int ks = 0; ks < 2; ks++) {
            const int kb = ks * 16;
            uint32_t af[4][4];
#pragma unroll
            for (int mt = 0; mt < 4; mt++) {
                int row = warp_m + mt * 16 + g;
                af[mt][0] = *reinterpret_cast<const uint32_t*>(&As[row][kb + 2 * t]);
                af[mt][1] = *reinterpret_cast<const uint32_t*>(&As[row + 8][kb + 2 * t]);
                af[mt][2] = *reinterpret_cast<const uint32_t*>(&As[row][kb + 2 * t + 8]);
                af[mt][3] = *reinterpret_cast<const uint32_t*>(&As[row + 8][kb + 2 * t + 8]);
            }
            uint32_t bf[4][2];
#pragma unroll
            for (int nt = 0; nt < 4; nt++) {
                int col = warp_n + nt * 8 + g;
                bf[nt][0] = *reinterpret_cast<const uint32_t*>(&Bs[col][kb + 2 * t]);
                bf[nt][1] = *reinterpret_cast<const uint32_t*>(&Bs[col][kb + 2 * t + 8]);
            }
#pragma unroll
            for (int mt = 0; mt < 4; mt++)
#pragma unroll
                for (int nt = 0; nt < 4; nt++) {
                    asm volatile(
                        "mma.sync.aligned.m16n8k16.row.col.f32.f16.f16.f32 "
                        "{%0,%1,%2,%3}, {%4,%5,%6,%7}, {%8,%9}, {%0,%1,%2,%3};"
                        : "+f"(acc[mt][nt][0]), "+f"(acc[mt][nt][1]),
                          "+f"(acc[mt][nt][2]), "+f"(acc[mt][nt][3])
                        : "r"(af[mt][0]), "r"(af[mt][1]), "r"(af[mt][2]), "r"(af[mt][3]),
                          "r"(bf[nt][0]), "r"(bf[nt][1]));
                }
        }
        __syncthreads();
    }

#pragma unroll
    for (int mt = 0; mt < 4; mt++) {
#pragma unroll
        for (int nt = 0; nt < 4; nt++) {
            int col = bc + warp_n + nt * 8 + t * 2;
            int rel = col >> 6;
            int o   = col & 63;
            int row0 = bm + warp_m + mt * 16 + g;
            if (row0 < N_NODES) {
                __half2* p = reinterpret_cast<__half2*>(
                    g_xw + ((size_t)rel * N_NODES + row0) * OUT_F + o);
                *p = __floats2half2_rn(acc[mt][nt][0], acc[mt][nt][1]);
            }
            int row1 = row0 + 8;
            if (row1 < N_NODES) {
                __half2* p = reinterpret_cast<__half2*>(
                    g_xw + ((size_t)rel * N_NODES + row1) * OUT_F + o);
                *p = __floats2half2_rn(acc[mt][nt][2], acc[mt][nt][3]);
            }
        }
    }
}

// ---------------------------------------------------------------------------
// Reduce: one warp per node, 4 edges per memory wave, uint4 (16B) per lane.
// Lane = 8*quarter + c: quarter picks the edge within the group of 4,
// c in 0..7 covers output cols 8c..8c+7 (8 halves = one uint4).
// Main loop: 16 edges = 4 independent uint4 loads per lane (deep MLP).
// Tail: ONE predicated batch (no serialized dependent waves).
// shfl_xor(8,16) combines quarters; quarter 0 stores 2 float4s (256B/warp).
// ---------------------------------------------------------------------------
__global__ __launch_bounds__(256)
void reduce_kernel(float* __restrict__ out) {
    int warp = (blockIdx.x * 256 + threadIdx.x) >> 5;   // node id, exact cover
    int lane = threadIdx.x & 31;
    int quarter = lane >> 3;   // 0..3
    int c = lane & 7;          // 0..7
    int beg = g_off[warp];
    int end = g_off[warp + 1];

    const uint4* xw16 = reinterpret_cast<const uint4*>(g_xw);   // row stride 8
    float a[8] = {0.f, 0.f, 0.f, 0.f, 0.f, 0.f, 0.f, 0.f};

#define ADDQ(q) { \
    float2 _f0 = __half22float2(*reinterpret_cast<const __half2*>(&(q).x)); \
    float2 _f1 = __half22float2(*reinterpret_cast<const __half2*>(&(q).y)); \
    float2 _f2 = __half22float2(*reinterpret_cast<const __half2*>(&(q).z)); \
    float2 _f3 = __half22float2(*reinterpret_cast<const __half2*>(&(q).w)); \
    a[0] += _f0.x; a[1] += _f0.y; a[2] += _f1.x; a[3] += _f1.y; \
    a[4] += _f2.x; a[5] += _f2.y; a[6] += _f3.x; a[7] += _f3.y; }

    int j = beg;
    for (; j + 16 <= end; j += 16) {
        uint4 q[4];
#pragma unroll
        for (int u = 0; u < 4; u++) {
            int p = g_perm[j + u * 4 + quarter];
            q[u] = xw16[(size_t)p * 8 + c];
        }
#pragma unroll
        for (int u = 0; u < 4; u++) ADDQ(q[u]);
    }
    if (j < end) {   // tail < 16 edges: one predicated, fully parallel batch
        uint4 q[4];
#pragma unroll
        for (int u = 0; u < 4; u++) {
            int e = j + u * 4 + quarter;
            if (e < end) {
                int p = g_perm[e];
                q[u] = xw16[(size_t)p * 8 + c];
            } else {
                q[u] = make_uint4(0u, 0u, 0u, 0u);
            }
        }
#pragma unroll
        for (int u = 0; u < 4; u++) ADDQ(q[u]);
    }
#undef ADDQ

#pragma unroll
    for (int i = 0; i < 8; i++) {
        a[i] += __shfl_xor_sync(0xFFFFFFFFu, a[i], 8);
        a[i] += __shfl_xor_sync(0xFFFFFFFFu, a[i], 16);
    }

    if (quarter == 0) {
        float4* po = reinterpret_cast<float4*>(out + (size_t)warp * OUT_F + c * 8);
        po[0] = make_float4(a[0], a[1], a[2], a[3]);
        po[1] = make_float4(a[4], a[5], a[6], a[7]);
    }
}

extern "C" void kernel_launch(void* const* d_in, const int* in_sizes, int n_in,
                              void* d_out, int out_size) {
    const float* feat = (const float*)d_in[0];
    const float* W    = (const float*)d_in[1];
    const int* esrc   = (const int*)d_in[2];
    const int* edst   = (const int*)d_in[3];
    const int* etyp   = (const int*)d_in[4];
    float* out        = (float*)d_out;

    const int nb_edge = (N_EDGES + 255) / 256;   // 6400

    // Fork a side stream for the CSR build so it overlaps the GEMM.
    cudaStream_t s1;
    cudaEvent_t evFork, evJoin;
    cudaStreamCreateWithFlags(&s1, cudaStreamNonBlocking);
    cudaEventCreateWithFlags(&evFork, cudaEventDisableTiming);
    cudaEventCreateWithFlags(&evJoin, cudaEventDisableTiming);

    cudaEventRecord(evFork, 0);
    cudaStreamWaitEvent(s1, evFork, 0);

    // side stream: CSR build by destination
    hist_kernel<<<nb_edge, 256, 0, s1>>>(edst);
    scan1_kernel<<<SCAN_BLOCKS, 256, 0, s1>>>();
    scan2_kernel<<<1, 512, 0, s1>>>();
    scan3_kernel<<<SCAN_BLOCKS, 256, 0, s1>>>();
    fill_kernel<<<nb_edge, 256, 0, s1>>>(esrc, edst, etyp);
    cudaEventRecord(evJoin, s1);

    // main stream: GEMM with fused fp32->fp16 convert
    dim3 ggrid(COLS / 128, (N_NODES + 127) / 128);   // (4, 782)
    gemm_mma_kernel<<<ggrid, 256>>>(feat, W);

    // join, then gather + register reduce per destination node
    cudaStreamWaitEvent(0, evJoin, 0);
    reduce_kernel<<<(N_NODES * 32) / 256, 256>>>(out);
}